// round 16
// baseline (speedup 1.0000x reference)
#include <cuda_runtime.h>
#include <math.h>
#include <stdint.h>

#define BB 64
#define TD 128
#define TE 256
#define DX 1024
#define HH 1024
#define N3 3072

// ---------------- persistent state (device globals; no allocations) ----------------
__device__ float g_h[2][BB * HH];       // ping-pong GRU state
__device__ float g_ifeed[BB * HH];
__device__ float g_feed[BB * HH];
__device__ float g_value[BB * HH];
__device__ float g_fp[4][BB * HH];      // FEED k-split partials
__device__ float g_gxp[4][BB * N3];     // gx k-split partials
__device__ float g_ghp[4][BB * N3];     // gh k-split partials
__device__ float g_hattp[8][BB * HH];   // HATT partials (y*4+z)
__device__ float g_attv[4][BB * HH];    // attention value partials (unnormalized)
__device__ float g_attm[4][BB];         // attention local max
__device__ float g_atts[4][BB];         // attention local expsum
__device__ float g_gxx[(size_t)TD * BB * N3];  // 96MB: x_t @ Wx[1024:] + bxi

// spin-group counters (self-resetting via depart tickets; start and end at 0)
__device__ int g_cnt_feed[32];
__device__ int g_cnt_attn[BB];
__device__ int g_cnt_hatt[32];

__global__ void init64(const float* __restrict__ h_enc) {
    int i = blockIdx.x * blockDim.x + threadIdx.x;
    if (i < BB * HH) { g_h[0][i] = h_enc[i]; g_ifeed[i] = 0.0f; }
}

__device__ __forceinline__ void ffma2(unsigned long long& a,
                                      unsigned long long x, unsigned long long y) {
    asm("fma.rn.f32x2 %0, %1, %2, %0;" : "+l"(a) : "l"(x), "l"(y));
}
__device__ __forceinline__ unsigned long long fadd2(unsigned long long x,
                                                    unsigned long long y) {
    unsigned long long d;
    asm("add.rn.f32x2 %0, %1, %2;" : "=l"(d) : "l"(x), "l"(y));
    return d;
}
__device__ __forceinline__ float lo2(unsigned long long v) {
    return __uint_as_float((unsigned)(v & 0xffffffffull));
}
__device__ __forceinline__ float hi2(unsigned long long v) {
    return __uint_as_float((unsigned)(v >> 32));
}

// spin-group arrive: all threads fenced + synced BEFORE call; tid0 arrives and
// spins until all `n` group members arrived. Followed by __syncthreads by caller.
__device__ __forceinline__ void group_arrive_wait(int* cnt, int n) {
    atomicAdd(cnt, 1);
    while (atomicAdd(cnt, 0) < n) { }
}
// spin-group depart: tid0 only; last departer resets the counter to 0.
__device__ __forceinline__ void group_depart(int* cnt, int n) {
    int t1 = atomicAdd(cnt, 1);
    if (t1 == 2 * n - 1) atomicExch(cnt, 0);
}

// ---------------- FFMA2 GEMM core (champion inner loop, VERBATIM) -------------------
// Block 256 thr = 2 in-block k-halves (kh) x 128 positions. C tile 64m x 32n.
// Thread tile 4m x 4n strided; 16 f32x2 k-pair accumulators.
// MODE 0 PRE : g_gxx[y] = x[:,y,:] @ Wx[1024:] + bxi     grid (96, TD)
// MODE 1 FEED: g_fp[y]  = ifeed[:, y*256:] @ Wfeed[sl]   grid (32, 4)  + feedcomb tail
// MODE 2 GXGH: y 0/1 gx/gh; z k-quarter                  grid (96, 2, 4)
// MODE 3 HATT: y value/h half; z k-quarter               grid (32, 2, 4) + combine tail
template <int MODE>
__global__ __launch_bounds__(256, 2)
void gk2(const float* __restrict__ pA, const float* __restrict__ pW,
         const float* __restrict__ pW2, const float* __restrict__ pBias, int hsel)
{
    constexpr int KW   = (MODE == 0) ? 1024 : 256;
    constexpr int KH   = KW / 2;
    constexpr int CH   = KH / 32;
    constexpr int NDIM = (MODE == 0 || MODE == 2) ? N3 : HH;

    __shared__ __align__(16) float2 sA2[2][2][16 * 64];   // 32KB
    __shared__ __align__(16) float2 sW2[2][2][16 * 32];   // 16KB

    const int tid = threadIdx.x;
    const int kh  = tid >> 7;
    const int p   = tid & 127;
    const int mg  = p & 15;
    const int ng  = p >> 4;
    const int n0  = blockIdx.x * 32;

    const float* A; size_t lda = HH;
    const float* W = pW;
    int kA = 0, kW2 = 0;
    float* C; size_t ldc;

    if (MODE == 0) {
        A = pA + (size_t)blockIdx.y * DX; lda = (size_t)TD * DX;
        C = g_gxx + (size_t)blockIdx.y * BB * N3; ldc = N3;
    } else if (MODE == 1) {
        const int z = blockIdx.y;
        A = g_ifeed; kA = kW2 = z * 256;
        C = g_fp[z]; ldc = HH;
    } else if (MODE == 2) {
        const int z = blockIdx.z;
        kA = kW2 = z * 256;
        if (blockIdx.y == 0) { A = g_feed;     W = pW;  C = g_gxp[z]; }
        else                 { A = g_h[hsel];  W = pW2; C = g_ghp[z]; }
        ldc = N3;
    } else {
        const int y = blockIdx.y, z = blockIdx.z;
        A = y ? g_h[hsel] : g_value;
        kA = z * 256; kW2 = y * HH + z * 256;
        C = g_hattp[y * 4 + z]; ldc = HH;
    }

    const int kbA = kA + kh * KH;
    const int kbW = kW2 + kh * KH;

    float4 ra[4];
    float2 rw[4];

    auto ldg = [&](int c) {
        const int kc = kbA + c * 32;
        #pragma unroll
        for (int i = 0; i < 4; ++i) {
            int idx = i * 128 + p;
            int m = idx >> 3, kq = idx & 7;
            ra[i] = *reinterpret_cast<const float4*>(A + (size_t)m * lda + kc + kq * 4);
        }
        const int kw = kbW + c * 32;
        #pragma unroll
        for (int i = 0; i < 4; ++i) {
            int idx = i * 128 + p;
            int n = idx & 31, kp = idx >> 5;
            rw[i].x = W[(size_t)(kw + 2 * kp)     * NDIM + n0 + n];
            rw[i].y = W[(size_t)(kw + 2 * kp + 1) * NDIM + n0 + n];
        }
    };
    auto sts = [&](int b) {
        float2* sa = sA2[kh][b];
        float2* sw = sW2[kh][b];
        #pragma unroll
        for (int i = 0; i < 4; ++i) {
            int idx = i * 128 + p;
            int m = idx >> 3, kq = idx & 7;
            int kp0 = 2 * kq, kp1 = 2 * kq + 1;
            sa[kp0 * 64 + (m ^ kp0)] = make_float2(ra[i].x, ra[i].y);
            sa[kp1 * 64 + (m ^ kp1)] = make_float2(ra[i].z, ra[i].w);
        }
        #pragma unroll
        for (int i = 0; i < 4; ++i) {
            int idx = i * 128 + p;
            int n = idx & 31, kp = idx >> 5;
            sw[kp * 32 + n] = rw[i];
        }
    };

    unsigned long long acc[4][4];
    #pragma unroll
    for (int mi = 0; mi < 4; ++mi)
        #pragma unroll
        for (int ni = 0; ni < 4; ++ni) acc[mi][ni] = 0ull;

    ldg(0); sts(0); __syncthreads();

    #pragma unroll 1
    for (int c = 0; c < CH; ++c) {
        if (c + 1 < CH) ldg(c + 1);
        const float2* sa = sA2[kh][c & 1];
        const float2* sw = sW2[kh][c & 1];
        #pragma unroll
        for (int kp = 0; kp < 16; ++kp) {
            const int mgx = mg ^ kp;
            unsigned long long av[4], wv[4];
            #pragma unroll
            for (int mi = 0; mi < 4; ++mi)
                av[mi] = *reinterpret_cast<const unsigned long long*>(
                    &sa[kp * 64 + mgx + 16 * mi]);
            #pragma unroll
            for (int ni = 0; ni < 4; ++ni)
                wv[ni] = *reinterpret_cast<const unsigned long long*>(
                    &sw[kp * 32 + ng + 8 * ni]);
            #pragma unroll
            for (int mi = 0; mi < 4; ++mi)
                #pragma unroll
                for (int ni = 0; ni < 4; ++ni)
                    ffma2(acc[mi][ni], av[mi], wv[ni]);
        }
        if (c + 1 < CH) sts((c + 1) & 1);
        __syncthreads();
    }

    unsigned long long* red = reinterpret_cast<unsigned long long*>(&sA2[0][0][0]);
    if (kh == 1) {
        unsigned long long* d = red + (size_t)p * 17;
        #pragma unroll
        for (int mi = 0; mi < 4; ++mi)
            #pragma unroll
            for (int ni = 0; ni < 4; ++ni) d[mi * 4 + ni] = acc[mi][ni];
    }
    __syncthreads();
    if (kh == 0) {
        const unsigned long long* s = red + (size_t)p * 17;
        #pragma unroll
        for (int mi = 0; mi < 4; ++mi) {
            #pragma unroll
            for (int ni = 0; ni < 4; ++ni) {
                unsigned long long tv = fadd2(acc[mi][ni], s[mi * 4 + ni]);
                float v = lo2(tv) + hi2(tv);
                const int m = mg + 16 * mi;
                const int n = n0 + ng + 8 * ni;
                if (MODE == 0) v += pBias[n];
                C[(size_t)m * ldc + n] = v;
            }
        }
    }

    // ---- MODE 1 tail: feedcomb fused (group = 4 z-blocks of this n-tile) ----
    if (MODE == 1) {
        __syncthreads();
        __threadfence();
        int* cnt = &g_cnt_feed[blockIdx.x];
        if (tid == 0) group_arrive_wait(cnt, 4);
        __syncthreads();
        const int zz = blockIdx.y;      // this block combines rows zz*16..zz*16+15
        #pragma unroll
        for (int i = tid; i < 512; i += 256) {
            int m = zz * 16 + (i >> 5);
            int n = n0 + (i & 31);
            int idx = m * HH + n;
            g_feed[idx] = tanhf(g_fp[0][idx] + g_fp[1][idx] + g_fp[2][idx]
                                + g_fp[3][idx] + pBias[n]);
        }
        if (tid == 0) group_depart(cnt, 4);
    }

    // ---- MODE 3 tail: combine_hatt fused (group = 8 (y,z)-blocks of this n-tile) ---
    if (MODE == 3) {
        __syncthreads();
        __threadfence();
        int* cnt = &g_cnt_hatt[blockIdx.x];
        if (tid == 0) group_arrive_wait(cnt, 8);
        __syncthreads();
        const int r = blockIdx.y * 4 + blockIdx.z;   // combines rows r*8..r*8+7
        {
            int m = r * 8 + (tid >> 5);
            int n = n0 + (tid & 31);
            int idx = m * HH + n;
            float v = g_hattp[0][idx] + g_hattp[1][idx] + g_hattp[2][idx]
                    + g_hattp[3][idx] + g_hattp[4][idx] + g_hattp[5][idx]
                    + g_hattp[6][idx] + g_hattp[7][idx] + pBias[n];
            v = tanhf(v);
            float* outp = const_cast<float*>(pA);    // out + t*HH
            outp[(size_t)m * (TD * HH) + n] = v;
            g_ifeed[idx] = v;
        }
        if (tid == 0) group_depart(cnt, 8);
    }
}

// ---------------- fused GRU + partial attention + attnc tail ------------------------
__global__ __launch_bounds__(512, 2)
void attnp(const float* __restrict__ o_enc, const float* __restrict__ bhr, int t)
{
    __shared__ __align__(16) float sh[HH];
    __shared__ float sp[64];
    __shared__ float red[8];

    const int b = blockIdx.x;
    const int z = blockIdx.y;
    const int tid = threadIdx.x;
    const int w = tid >> 5;
    const int l = tid & 31;
    const int hsel = t & 1;

    const float* gxx = g_gxx + (size_t)t * BB * N3 + (size_t)b * N3;
    const float* hcur = g_h[hsel];
    float* hnxt = g_h[hsel ^ 1];

    // phase 1: sum GEMM partials + GRU elementwise (reset_after=True)
    #pragma unroll
    for (int r = 0; r < 2; ++r) {
        int i = (r << 9) + tid;
        int i0 = b * N3 + i, i1 = i0 + HH, i2 = i0 + 2 * HH;
        float xz  = g_gxp[0][i0] + g_gxp[1][i0] + g_gxp[2][i0] + g_gxp[3][i0] + gxx[i];
        float xr  = g_gxp[0][i1] + g_gxp[1][i1] + g_gxp[2][i1] + g_gxp[3][i1] + gxx[HH + i];
        float xh  = g_gxp[0][i2] + g_gxp[1][i2] + g_gxp[2][i2] + g_gxp[3][i2] + gxx[2 * HH + i];
        float hz  = g_ghp[0][i0] + g_ghp[1][i0] + g_ghp[2][i0] + g_ghp[3][i0] + bhr[i];
        float hr  = g_ghp[0][i1] + g_ghp[1][i1] + g_ghp[2][i1] + g_ghp[3][i1] + bhr[HH + i];
        float hh2 = g_ghp[0][i2] + g_ghp[1][i2] + g_ghp[2][i2] + g_ghp[3][i2] + bhr[2 * HH + i];
        float hp  = hcur[b * HH + i];
        float zz = 1.0f / (1.0f + expf(-(xz + hz)));
        float rr = 1.0f / (1.0f + expf(-(xr + hr)));
        float hc = tanhf(xh + rr * hh2);
        float hn = zz * hp + (1.0f - zz) * hc;
        sh[i] = hn;
        if (z == 0) hnxt[b * HH + i] = hn;
    }
    __syncthreads();

    // phase 2: scores for this z's 64 rows (16 warps x 4 rows)
    const float* ob = o_enc + (size_t)b * TE * HH;
    #pragma unroll
    for (int tt = 0; tt < 4; ++tt) {
        int tl = (w << 2) + tt;
        const float* orow = ob + (z * 64 + tl) * HH;
        float s = 0.0f;
        #pragma unroll
        for (int jj = 0; jj < 8; ++jj) {
            int i = (jj << 7) + (l << 2);
            float4 o4 = *reinterpret_cast<const float4*>(orow + i);
            float4 h4 = *reinterpret_cast<const float4*>(sh + i);
            s += o4.x * h4.x + o4.y * h4.y + o4.z * h4.z + o4.w * h4.w;
        }
        #pragma unroll
        for (int off = 16; off > 0; off >>= 1)
            s += __shfl_xor_sync(0xffffffffu, s, off);
        if (l == 0) sp[tl] = s;
    }
    __syncthreads();

    // phase 3: local softmax stats over 64 scores
    float v = 0.0f;
    if (tid < 64) {
        v = sp[tid];
        float M = v;
        #pragma unroll
        for (int off = 16; off > 0; off >>= 1)
            M = fmaxf(M, __shfl_xor_sync(0xffffffffu, M, off));
        if (l == 0) red[w] = M;
    }
    __syncthreads();
    const float M = fmaxf(red[0], red[1]);
    if (tid < 64) {
        float e = expf(v - M);
        float S = e;
        #pragma unroll
        for (int off = 16; off > 0; off >>= 1)
            S += __shfl_xor_sync(0xffffffffu, S, off);
        if (l == 0) red[2 + w] = S;
        sp[tid] = e;
    }
    __syncthreads();
    if (tid == 0) { g_attm[z][b] = M; g_atts[z][b] = red[2] + red[3]; }

    // phase 4: unnormalized value partial
    float2 a = make_float2(0.f, 0.f);
    const int col = tid << 1;
    const float* obz = ob + z * 64 * HH;
    #pragma unroll 4
    for (int te = 0; te < 64; ++te) {
        float pp = sp[te];
        float2 o2 = *reinterpret_cast<const float2*>(obz + te * HH + col);
        a.x = fmaf(pp, o2.x, a.x);
        a.y = fmaf(pp, o2.y, a.y);
    }
    *reinterpret_cast<float2*>(&g_attv[z][b * HH + col]) = a;

    // ---- attnc tail (group = 4 z-blocks of this batch row) ----
    __syncthreads();
    __threadfence();
    int* cnt = &g_cnt_attn[b];
    if (tid == 0) group_arrive_wait(cnt, 4);
    __syncthreads();
    if (tid < 256) {
        float m0 = g_attm[0][b], m1 = g_attm[1][b], m2 = g_attm[2][b], m3 = g_attm[3][b];
        float Mb = fmaxf(fmaxf(m0, m1), fmaxf(m2, m3));
        float c0 = expf(m0 - Mb), c1 = expf(m1 - Mb);
        float c2 = expf(m2 - Mb), c3 = expf(m3 - Mb);
        float inv = 1.0f / (g_atts[0][b] * c0 + g_atts[1][b] * c1 +
                            g_atts[2][b] * c2 + g_atts[3][b] * c3);
        int cc = z * 256 + tid;          // this z combines cols z*256..z*256+255
        float vv = (g_attv[0][b * HH + cc] * c0 + g_attv[1][b * HH + cc] * c1 +
                    g_attv[2][b * HH + cc] * c2 + g_attv[3][b * HH + cc] * c3) * inv;
        g_value[b * HH + cc] = vv;
    }
    if (tid == 0) group_depart(cnt, 4);
}

// ---------------- launcher ----------------------------------------------------------
extern "C" void kernel_launch(void* const* d_in, const int* in_sizes, int n_in,
                              void* d_out, int out_size)
{
    const float* x      = (const float*)d_in[0];
    const float* o_enc  = (const float*)d_in[1];
    const float* h_enc  = (const float*)d_in[2];
    const float* Wfeed  = (const float*)d_in[3];
    const float* bfeed  = (const float*)d_in[4];
    const float* Wx     = (const float*)d_in[5];
    const float* Wh     = (const float*)d_in[6];
    const float* bxi    = (const float*)d_in[7];
    const float* bhr    = (const float*)d_in[8];
    const float* Watt   = (const float*)d_in[9];
    const float* batt   = (const float*)d_in[10];
    float* out = (float*)d_out;

    init64<<<64, 1024>>>(h_enc);

    // precompute g_gxx[t] = x_t @ Wx[1024:] + bxi (recurrence-independent)
    gk2<0><<<dim3(96, TD), 256>>>(x, Wx + (size_t)HH * N3, nullptr, bxi, 0);

    for (int t = 0; t < TD; ++t) {
        // FEED partials + fused feedcomb tail
        gk2<1><<<dim3(32, 4), 256>>>(nullptr, Wfeed, nullptr, bfeed, 0);
        // gx + gh (k-quarters)
        gk2<2><<<dim3(96, 2, 4), 256>>>(nullptr, Wx, Wh, nullptr, t & 1);
        // GRU + partial attention + fused attnc tail (writes h[t+1], g_value)
        attnp<<<dim3(BB, 4), 512>>>(o_enc, bhr, t);
        // HATT partials + fused combine tail (writes out[:,t,:], g_ifeed)
        gk2<3><<<dim3(32, 2, 4), 256>>>((const float*)(out + (size_t)t * HH),
                                        Watt, nullptr, batt, (t + 1) & 1);
    }
}